// round 7
// baseline (speedup 1.0000x reference)
#include <cuda_runtime.h>
#include <stdint.h>

// Problem constants (fixed by the reference)
#define SEQ_LEN   2048
#define NUM_HEADS 16
#define BATCH     2
#define BIAS_PITCH 4096   // 2*SEQ_LEN-1 = 4095, padded to 4096

// Scratch: per-head bias indexed by t = (i - j) + (S-1)
//   t >= S-1  -> e1[t-(S-1), h]
//   t <  S-1  -> e2[(S-2)-t,  h]
__device__ float g_bias[NUM_HEADS * BIAS_PITCH];

__global__ void build_bias_kernel(const float* __restrict__ e1,
                                  const float* __restrict__ e2) {
    int idx = blockIdx.x * blockDim.x + threadIdx.x;
    const int total = NUM_HEADS * (2 * SEQ_LEN - 1);
    if (idx >= total) return;
    int h = idx / (2 * SEQ_LEN - 1);
    int t = idx - h * (2 * SEQ_LEN - 1);
    float v;
    if (t >= SEQ_LEN - 1) {
        v = e1[(t - (SEQ_LEN - 1)) * NUM_HEADS + h];
    } else {
        v = e2[((SEQ_LEN - 2) - t) * NUM_HEADS + h];
    }
    g_bias[h * BIAS_PITCH + t] = v;
}

// One float4 store per thread; batch is the slowest tid dimension so the
// output offset equals tid exactly -> one purely linear write stream per warp.
// (Resubmission of R6 kernel after infra-only container failure.)
__global__ __launch_bounds__(256)
void write_out_kernel(float4* __restrict__ out) {
    // tid layout: j4 fastest (512), then i (2048), then h (16), then b (2)
    unsigned tid = blockIdx.x * blockDim.x + threadIdx.x;
    unsigned j4 = tid & 511u;            // tid % 512
    unsigned rem = tid >> 9;
    unsigned i = rem & 2047u;            // i
    unsigned h = (rem >> 11) & 15u;      // h (batch bit above it is ignored for bias)

    int j0 = (int)(j4 << 2);
    // t for j = j0: t = i - j0 + (S-1); accesses t, t-1, t-2, t-3.
    // Range: i in [0,2047], j0 in [0,2044] -> t in [3, 4094]; t-3 >= 0. In bounds.
    const float* __restrict__ bh =
        g_bias + h * BIAS_PITCH + ((int)i - j0 + (SEQ_LEN - 1));

    float4 v;
    v.x = bh[0];
    v.y = bh[-1];
    v.z = bh[-2];
    v.w = bh[-3];

    // off == tid by construction of the layout
    __stcs(&out[tid], v);
}

extern "C" void kernel_launch(void* const* d_in, const int* in_sizes, int n_in,
                              void* d_out, int out_size) {
    // metadata order: q (unused), e1, e2
    const float* e1 = (const float*)d_in[1];
    const float* e2 = (const float*)d_in[2];
    float4* out = (float4*)d_out;

    {
        const int total = NUM_HEADS * (2 * SEQ_LEN - 1);
        int threads = 256;
        int blocks = (total + threads - 1) / threads;
        build_bias_kernel<<<blocks, threads>>>(e1, e2);
    }
    {
        // threads = B * H * S * (S/4) = 2 * 16 * 2048 * 512 = 33,554,432
        unsigned total = BATCH * NUM_HEADS * SEQ_LEN * (SEQ_LEN / 4);
        int threads = 256;
        unsigned blocks = total / threads;   // 131072
        write_out_kernel<<<blocks, threads>>>(out);
    }
}

// round 9
// speedup vs baseline: 1.3722x; 1.3722x over previous
#include <cuda_runtime.h>
#include <stdint.h>

// Problem constants (fixed by the reference)
#define SEQ_LEN   2048
#define NUM_HEADS 16
#define BATCH     2
#define RB_PITCH  4096   // floats per (h, m) reversed-bias copy

// Reversed bias, 4 pre-shifted copies per head for warp-uniform alignment:
//   rev[h][u] = bias(delta = 2047 - u):  u <= 2047 -> e1[2047-u, h]
//                                        u >= 2048 -> e2[u-2048, h]
//   g_rb[(h*4 + m)*RB_PITCH + x] = rev[h][x + m]   (m in 0..3)
// Total 16*4*4096*4B = 1 MiB (L2-resident).
// (Resubmission of R8 kernel after infra-only container failure.)
__device__ float g_rb[NUM_HEADS * 4 * RB_PITCH];

__global__ void build_bias_kernel(const float* __restrict__ e1,
                                  const float* __restrict__ e2) {
    int idx = blockIdx.x * blockDim.x + threadIdx.x;          // [0, 16*4*4096)
    const int total = NUM_HEADS * 4 * RB_PITCH;
    if (idx >= total) return;
    int x = idx & (RB_PITCH - 1);
    int hm = idx >> 12;           // h*4 + m
    int m = hm & 3;
    int h = hm >> 2;
    int u = x + m;                // reversed index
    float v = 0.0f;
    if (u <= 2 * SEQ_LEN - 2) {   // u in [0, 4094]
        if (u <= SEQ_LEN - 1) {
            v = e1[(SEQ_LEN - 1 - u) * NUM_HEADS + h];        // delta = 2047-u >= 0
        } else {
            v = e2[(u - SEQ_LEN) * NUM_HEADS + h];            // j > i side
        }
    }
    g_rb[idx] = v;
}

// Each thread: ONE aligned float4 read (forward-contiguous bias for j0..j0+3),
// TWO coalesced float4 streaming stores (batch 0 and batch 1 planes).
__global__ __launch_bounds__(256)
void write_out_kernel(float4* __restrict__ out) {
    // tid layout: j4 fastest (512), then i (2048), then h (16)
    unsigned tid = blockIdx.x * blockDim.x + threadIdx.x;
    unsigned j4 = tid & 511u;
    unsigned rem = tid >> 9;
    unsigned i = rem & 2047u;
    unsigned h = rem >> 11;

    // u0 = j0 + d, d = 2047 - i; split d = 4*q + m (m warp-uniform).
    unsigned d = 2047u - i;
    unsigned q = d >> 2;
    unsigned m = d & 3u;

    // float index of load: (h*4+m)*RB_PITCH + 4*(q + j4) + s, s=0..3.
    // Max: 4*(511+511)+3 = 4091 < RB_PITCH. In bounds, 16B-aligned.
    const float4* __restrict__ p =
        reinterpret_cast<const float4*>(g_rb + (size_t)(h * 4u + m) * RB_PITCH)
        + q + j4;
    float4 v = *p;   // v.x..v.w = bias(i, j0..j0+3)

    // out is float4-typed: 512 float4 per (h,i) row
    size_t row = (size_t)h * SEQ_LEN + i;                    // plane-row, batch 0
    size_t off0 = row * 512 + j4;
    size_t off1 = off0 + (size_t)NUM_HEADS * SEQ_LEN * 512;  // batch 1 plane

    __stcs(&out[off0], v);
    __stcs(&out[off1], v);
}

extern "C" void kernel_launch(void* const* d_in, const int* in_sizes, int n_in,
                              void* d_out, int out_size) {
    // metadata order: q (unused), e1, e2
    const float* e1 = (const float*)d_in[1];
    const float* e2 = (const float*)d_in[2];
    float4* out = (float4*)d_out;

    {
        const int total = NUM_HEADS * 4 * RB_PITCH;   // 262144
        int threads = 256;
        int blocks = total / threads;                 // 1024
        build_bias_kernel<<<blocks, threads>>>(e1, e2);
    }
    {
        // threads = H * S * (S/4) = 16 * 2048 * 512 = 16,777,216
        unsigned total = NUM_HEADS * SEQ_LEN * (SEQ_LEN / 4);
        int threads = 256;
        unsigned blocks = total / threads;            // 65536
        write_out_kernel<<<blocks, threads>>>(out);
    }
}